// round 5
// baseline (speedup 1.0000x reference)
#include <cuda_runtime.h>
#include <cstdint>

#define N_PTS   16384
#define B_SZ    8
#define NPT     512
#define KNB     32
#define NCH     128
#define R2      0.04f

// ---------------- device scratch (no runtime allocation allowed) ----------------
__device__ float g_n2   [B_SZ * N_PTS];              // per-point squared norms
__device__ int   g_idx  [B_SZ * NPT * KNB];          // ball-query neighbor lists
__device__ float g_featT[(size_t)B_SZ * N_PTS * NCH]; // features transposed to (B,N,C)

// ---------------- packed f32x2 helpers (two independent IEEE-rn ops) ------------
__device__ __forceinline__ unsigned long long f2_add(unsigned long long a, unsigned long long b) {
    unsigned long long r; asm("add.rn.f32x2 %0, %1, %2;" : "=l"(r) : "l"(a), "l"(b)); return r;
}
__device__ __forceinline__ unsigned long long f2_mul(unsigned long long a, unsigned long long b) {
    unsigned long long r; asm("mul.rn.f32x2 %0, %1, %2;" : "=l"(r) : "l"(a), "l"(b)); return r;
}
__device__ __forceinline__ unsigned long long f2_pack(float lo, float hi) {
    unsigned long long r; asm("mov.b64 %0, {%1, %2};" : "=l"(r) : "f"(lo), "f"(hi)); return r;
}
__device__ __forceinline__ void f2_unpack(float& lo, float& hi, unsigned long long v) {
    asm("mov.b64 {%0, %1}, %2;" : "=f"(lo), "=f"(hi) : "l"(v));
}

// =================================================================================
// Kernel 1: FPS — one CTA per batch, 1024 threads, 16 pts/thread.
// x,y packed in registers (f32x2), z in skewed shared memory, dists in registers.
// Exact arithmetic: d = ((dx*dx + dy*dy) + dz*dz), plain rn mul/add (no FMA).
// Argmax via REDUX: per-thread fmax chain -> warp redux.max(u32 bits; dists >= 0 so
// the u32 order == float order) -> cross-warp redux over smem -> only matching
// thread(s) scan their 16 dists for the first index; min-index redux for ties.
// =================================================================================
extern __shared__ float zsh[];  // N_PTS + 2*(N_PTS/32) floats

__global__ void __launch_bounds__(1024, 1)
fps_kernel(const float* __restrict__ xyz, float* __restrict__ out_newxyz)
{
    const int b    = blockIdx.x;
    const int t    = threadIdx.x;
    const int lane = t & 31;
    const int wid  = t >> 5;
    const float* X = xyz + (size_t)b * N_PTS * 3;

    __shared__ unsigned s_w[32];
    __shared__ int      s_i[32];

    unsigned long long xq[8], yq[8];
    float pd[16];
    const int base = t * 16;
    // skew: z index = p + 2*(p>>5); for p in [16t,16t+15], p>>5 == t>>1 (constant)
    float* zp = zsh + base + (t & ~1);

    #pragma unroll
    for (int k = 0; k < 8; k++) {
        const int p = base + 2 * k;
        const float x0 = X[3*p+0], y0 = X[3*p+1], z0 = X[3*p+2];
        const float x1 = X[3*p+3], y1 = X[3*p+4], z1 = X[3*p+5];
        xq[k] = f2_pack(x0, x1);
        yq[k] = f2_pack(y0, y1);
        zp[2*k]   = z0;
        zp[2*k+1] = z1;
        pd[2*k]   = 1e10f;
        pd[2*k+1] = 1e10f;
        g_n2[b*N_PTS + p]     = __fadd_rn(__fadd_rn(__fmul_rn(x0,x0), __fmul_rn(y0,y0)), __fmul_rn(z0,z0));
        g_n2[b*N_PTS + p + 1] = __fadd_rn(__fadd_rn(__fmul_rn(x1,x1), __fmul_rn(y1,y1)), __fmul_rn(z1,z1));
    }

    if (t == 0) {
        float* o = out_newxyz + (size_t)b * NPT * 3;
        o[0] = X[0]; o[1] = X[1]; o[2] = X[2];
    }
    int cur = 0;
    __syncthreads();

    for (int it = 0; it < NPT - 1; ++it) {
        const float cx = __ldg(X + 3*cur + 0);
        const float cy = __ldg(X + 3*cur + 1);
        const float cz = __ldg(X + 3*cur + 2);
        const unsigned long long ncx = f2_pack(-cx, -cx);
        const unsigned long long ncy = f2_pack(-cy, -cy);
        const unsigned long long ncz = f2_pack(-cz, -cz);

        float bestv = 0.0f;   // all dists >= +0

        #pragma unroll
        for (int k = 0; k < 8; k++) {
            const unsigned long long zz = *reinterpret_cast<const unsigned long long*>(zp + 2*k);
            const unsigned long long dx = f2_add(xq[k], ncx);
            const unsigned long long dy = f2_add(yq[k], ncy);
            const unsigned long long dz = f2_add(zz,    ncz);
            const unsigned long long s  =
                f2_add(f2_add(f2_mul(dx, dx), f2_mul(dy, dy)), f2_mul(dz, dz));
            float d0, d1;
            f2_unpack(d0, d1, s);
            const float v0 = fminf(pd[2*k],   d0); pd[2*k]   = v0;
            const float v1 = fminf(pd[2*k+1], d1); pd[2*k+1] = v1;
            bestv = fmaxf(bestv, fmaxf(v0, v1));
        }

        const unsigned bb   = __float_as_uint(bestv);
        const unsigned wmax = __reduce_max_sync(0xffffffffu, bb);
        if (lane == 0) s_w[wid] = wmax;
        __syncthreads();

        // all warps reduce the 32 per-warp maxima in parallel
        const unsigned gmax = __reduce_max_sync(0xffffffffu, s_w[lane]);

        int tidx = 0x7fffffff;
        if (bb == gmax) {                       // typically one thread per CTA
            const float gm = __uint_as_float(gmax);
            #pragma unroll
            for (int j = 15; j >= 0; --j)
                if (pd[j] == gm) tidx = base + j;   // reverse scan -> first (smallest) j
        }
        const int wmin = __reduce_min_sync(0xffffffffu, tidx);
        if (lane == 0) s_i[wid] = wmin;
        __syncthreads();

        cur = __reduce_min_sync(0xffffffffu, s_i[lane]);   // min index over ties

        if (t == 0) {
            float* o = out_newxyz + ((size_t)b * NPT + it + 1) * 3;
            o[0] = X[3*cur]; o[1] = X[3*cur+1]; o[2] = X[3*cur+2];
        }
    }
}

// =================================================================================
// Kernel 2: feature transpose (B,C,N) -> (B,N,C), tiled 32x32 through smem.
// =================================================================================
__global__ void __launch_bounds__(256)
transpose_kernel(const float* __restrict__ feat)
{
    __shared__ float tile[32][33];
    const int b  = blockIdx.z;
    const int n0 = blockIdx.x * 32;
    const int c0 = blockIdx.y * 32;
    const int tx = threadIdx.x, ty = threadIdx.y;

    const float* src = feat + (size_t)b * NCH * N_PTS;
    #pragma unroll
    for (int i = 0; i < 32; i += 8)
        tile[ty + i][tx] = src[(size_t)(c0 + ty + i) * N_PTS + n0 + tx];
    __syncthreads();

    float* dst = g_featT + (size_t)b * N_PTS * NCH;
    #pragma unroll
    for (int i = 0; i < 32; i += 8)
        dst[(size_t)(n0 + ty + i) * NCH + c0 + tx] = tile[tx][ty + i];
}

// =================================================================================
// Kernel 3: ball query — one warp per centroid, early exit after K found.
// Distance matches the reference's expanded form: d = ((-2*dot) + s2) + n2.
// Qualify iff !(d > r^2); first K in index order; pad with first.
// =================================================================================
__global__ void __launch_bounds__(256)
ball_kernel(const float* __restrict__ xyz, const float* __restrict__ newxyz)
{
    const int wig    = (blockIdx.x * 256 + threadIdx.x) >> 5;   // global warp id = b*512+s
    const int lane   = threadIdx.x & 31;
    const int wlocal = threadIdx.x >> 5;
    __shared__ int sid[8][KNB];

    const int b = wig >> 9;
    const float* C = newxyz + (size_t)wig * 3;
    const float cx = C[0], cy = C[1], cz = C[2];
    const float s2 = __fadd_rn(__fadd_rn(__fmul_rn(cx,cx), __fmul_rn(cy,cy)), __fmul_rn(cz,cz));

    const float* X  = xyz  + (size_t)b * N_PTS * 3;
    const float* NN = g_n2 + (size_t)b * N_PTS;

    int cnt = 0;
    for (int basep = 0; basep < N_PTS && cnt < KNB; basep += 32) {
        const int p = basep + lane;
        const float x = X[3*p], y = X[3*p+1], z = X[3*p+2];
        float dot = __fmul_rn(cx, x);
        dot = __fmaf_rn(cy, y, dot);
        dot = __fmaf_rn(cz, z, dot);
        const float d = __fadd_rn(__fadd_rn(__fmul_rn(-2.0f, dot), s2), NN[p]);
        const bool q = !(d > R2);
        const unsigned m = __ballot_sync(0xffffffffu, q);
        const int pos = cnt + __popc(m & ((1u << lane) - 1u));
        if (q && pos < KNB) sid[wlocal][pos] = p;
        cnt += __popc(m);
    }
    __syncwarp();

    const int first = sid[wlocal][0];          // cnt==0 impossible: centroid itself qualifies
    const int v = (lane < cnt) ? sid[wlocal][lane] : first;
    g_idx[(size_t)wig * KNB + lane] = v;
}

// =================================================================================
// Kernel 4: masked max pool from transposed features — block per (b,s), thread=c.
// Warp lanes read consecutive channels -> fully coalesced 128B gathers.
// =================================================================================
__global__ void __launch_bounds__(128)
pool_kernel(float* __restrict__ out)
{
    const int g = blockIdx.x;             // b*512 + s
    const int c = threadIdx.x;
    const int b = g >> 9;
    const int s = g & 511;

    __shared__ int nb[KNB];
    if (c < KNB) nb[c] = g_idx[(size_t)g * KNB + c];
    __syncthreads();

    const float* F = g_featT + (size_t)b * N_PTS * NCH;

    float m0 = F[(size_t)nb[0] * NCH + c];
    float m1 = F[(size_t)nb[1] * NCH + c];
    float m2 = F[(size_t)nb[2] * NCH + c];
    float m3 = F[(size_t)nb[3] * NCH + c];
    #pragma unroll
    for (int k = 4; k < KNB; k += 4) {
        m0 = fmaxf(m0, F[(size_t)nb[k]   * NCH + c]);
        m1 = fmaxf(m1, F[(size_t)nb[k+1] * NCH + c]);
        m2 = fmaxf(m2, F[(size_t)nb[k+2] * NCH + c]);
        m3 = fmaxf(m3, F[(size_t)nb[k+3] * NCH + c]);
    }
    const float m = fmaxf(fmaxf(m0, m1), fmaxf(m2, m3));

    out[(size_t)B_SZ*NPT*3 + ((size_t)b * NCH + c) * NPT + s] = m;
}

// =================================================================================
extern "C" void kernel_launch(void* const* d_in, const int* in_sizes, int n_in,
                              void* d_out, int out_size)
{
    const float* xyz  = (const float*)d_in[0];   // (8, 16384, 3) fp32
    const float* feat = (const float*)d_in[1];   // (8, 128, 16384) fp32
    float* out = (float*)d_out;                  // new_xyz (12288) ++ sub_features (524288)

    const int zsmem = (N_PTS + 2 * (N_PTS / 32)) * (int)sizeof(float);  // 69632 B
    cudaFuncSetAttribute(fps_kernel, cudaFuncAttributeMaxDynamicSharedMemorySize, zsmem);

    dim3 tgrid(N_PTS / 32, NCH / 32, B_SZ);
    dim3 tblk(32, 8);
    transpose_kernel<<<tgrid, tblk>>>(feat);
    fps_kernel <<<B_SZ, 1024, zsmem>>>(xyz, out);
    ball_kernel<<<(B_SZ * NPT * 32) / 256, 256>>>(xyz, out);
    pool_kernel<<<B_SZ * NPT, 128>>>(out);
}

// round 7
// speedup vs baseline: 1.6912x; 1.6912x over previous
#include <cuda_runtime.h>
#include <cstdint>

#define N_PTS   16384
#define B_SZ    8
#define NPT     512
#define KNB     32
#define NCH     128
#define R2      0.04f

#define CLUSTER 8
#define PTS_PER_CTA (N_PTS / CLUSTER)   // 2048
#define FPS_THR 512
#define PPT (PTS_PER_CTA / FPS_THR)     // 4 points per thread

// ---------------- device scratch (no runtime allocation allowed) ----------------
__device__ float g_n2   [B_SZ * N_PTS];               // per-point squared norms
__device__ int   g_idx  [B_SZ * NPT * KNB];           // ball-query neighbor lists
__device__ float g_featT[(size_t)B_SZ * N_PTS * NCH]; // features transposed to (B,N,C)

// ---------------- packed f32x2 helpers (two independent IEEE-rn ops) ------------
__device__ __forceinline__ unsigned long long f2_add(unsigned long long a, unsigned long long b) {
    unsigned long long r; asm("add.rn.f32x2 %0, %1, %2;" : "=l"(r) : "l"(a), "l"(b)); return r;
}
__device__ __forceinline__ unsigned long long f2_mul(unsigned long long a, unsigned long long b) {
    unsigned long long r; asm("mul.rn.f32x2 %0, %1, %2;" : "=l"(r) : "l"(a), "l"(b)); return r;
}
__device__ __forceinline__ unsigned long long f2_pack(float lo, float hi) {
    unsigned long long r; asm("mov.b64 %0, {%1, %2};" : "=l"(r) : "f"(lo), "f"(hi)); return r;
}
__device__ __forceinline__ void f2_unpack(float& lo, float& hi, unsigned long long v) {
    asm("mov.b64 {%0, %1}, %2;" : "=f"(lo), "=f"(hi) : "l"(v));
}
__device__ __forceinline__ uint32_t smem_u32(const void* p) {
    uint32_t a;
    asm("{ .reg .u64 t; cvta.to.shared.u64 t, %1; cvt.u32.u64 %0, t; }" : "=r"(a) : "l"(p));
    return a;
}

// =================================================================================
// Kernel 1: FPS — cluster of 8 CTAs per batch (64 CTAs total), 512 thr/CTA,
// 4 points/thread held ENTIRELY in registers (f32x2-packed). Per iteration:
//   1. min-update + per-thread max (exact arithmetic: d = ((dx*dx+dy*dy)+dz*dz),
//      plain rn ops, no FMA — identical to the bit-exact R3 form)
//   2. warp argmax via REDUX (max bits; dists>=0 so u32 order == float order;
//      tie -> min global index), candidate thread stages coords to smem
//   3. __syncthreads; warp0 selects CTA winner, writes (bits,idx,x,y,z) into
//      every cluster CTA's mailbox (mapa + st.shared::cluster, lanes 0..7
//      in parallel, double-buffered by iteration parity)
//   4. ONE barrier.cluster; every thread reduces the 8 mailbox entries ->
//      next centroid coords directly in registers.
// =================================================================================
__global__ void __launch_bounds__(FPS_THR, 1) __cluster_dims__(CLUSTER, 1, 1)
fps_kernel(const float* __restrict__ xyz, float* __restrict__ out_newxyz)
{
    const int rank = blockIdx.x;          // CTA rank within cluster (0..7)
    const int b    = blockIdx.y;          // batch
    const int t    = threadIdx.x;
    const int lane = t & 31;
    const int wid  = t >> 5;              // 0..15

    const float* X = xyz + (size_t)b * N_PTS * 3;

    __shared__ unsigned s_wv[16];
    __shared__ int      s_wi[16];
    __shared__ float    s_cand[16][3];
    __shared__ unsigned mbox[2][CLUSTER][6];   // bits, idx, x, y, z, pad

    const int base = rank * PTS_PER_CTA + t * PPT;   // first owned global point

    // ---- load 4 points (12 floats = 3x float4, 16B-aligned) ----
    const float4 q0 = *(const float4*)(X + (size_t)base * 3);
    const float4 q1 = *(const float4*)(X + (size_t)base * 3 + 4);
    const float4 q2 = *(const float4*)(X + (size_t)base * 3 + 8);
    // points: (q0.x q0.y q0.z) (q0.w q1.x q1.y) (q1.z q1.w q2.x) (q2.y q2.z q2.w)
    const float ax0 = q0.x, ay0 = q0.y, az0 = q0.z;
    const float ax1 = q0.w, ay1 = q1.x, az1 = q1.y;
    const float ax2 = q1.z, ay2 = q1.w, az2 = q2.x;
    const float ax3 = q2.y, ay3 = q2.z, az3 = q2.w;

    // squared norms for the ball-query kernel (exact square-then-sum)
    {
        float4 n;
        n.x = __fadd_rn(__fadd_rn(__fmul_rn(ax0,ax0), __fmul_rn(ay0,ay0)), __fmul_rn(az0,az0));
        n.y = __fadd_rn(__fadd_rn(__fmul_rn(ax1,ax1), __fmul_rn(ay1,ay1)), __fmul_rn(az1,az1));
        n.z = __fadd_rn(__fadd_rn(__fmul_rn(ax2,ax2), __fmul_rn(ay2,ay2)), __fmul_rn(az2,az2));
        n.w = __fadd_rn(__fadd_rn(__fmul_rn(ax3,ax3), __fmul_rn(ay3,ay3)), __fmul_rn(az3,az3));
        *(float4*)(g_n2 + (size_t)b * N_PTS + base) = n;
    }

    unsigned long long xq[2], yq[2], zq[2];
    xq[0] = f2_pack(ax0, ax1); xq[1] = f2_pack(ax2, ax3);
    yq[0] = f2_pack(ay0, ay1); yq[1] = f2_pack(ay2, ay3);
    zq[0] = f2_pack(az0, az1); zq[1] = f2_pack(az2, az3);
    float pd[4] = {1e10f, 1e10f, 1e10f, 1e10f};

    // initial centroid = point 0; emit row 0
    float cx = __ldg(X + 0), cy = __ldg(X + 1), cz = __ldg(X + 2);
    if (rank == 0 && t == 0) {
        float* o = out_newxyz + (size_t)b * NPT * 3;
        o[0] = cx; o[1] = cy; o[2] = cz;
    }

    for (int it = 0; it < NPT - 1; ++it) {
        const unsigned long long ncx = f2_pack(-cx, -cx);
        const unsigned long long ncy = f2_pack(-cy, -cy);
        const unsigned long long ncz = f2_pack(-cz, -cz);

        #pragma unroll
        for (int k = 0; k < 2; k++) {
            const unsigned long long dx = f2_add(xq[k], ncx);
            const unsigned long long dy = f2_add(yq[k], ncy);
            const unsigned long long dz = f2_add(zq[k], ncz);
            const unsigned long long s  =
                f2_add(f2_add(f2_mul(dx, dx), f2_mul(dy, dy)), f2_mul(dz, dz));
            float d0, d1;
            f2_unpack(d0, d1, s);
            pd[2*k]   = fminf(pd[2*k],   d0);
            pd[2*k+1] = fminf(pd[2*k+1], d1);
        }
        const float bestv = fmaxf(fmaxf(pd[0], pd[1]), fmaxf(pd[2], pd[3]));
        const unsigned bb = __float_as_uint(bestv);     // dists >= +0: u32 order == float order

        const unsigned wmax = __reduce_max_sync(0xffffffffu, bb);
        int tidx = 0x7fffffff;
        if (bb == wmax) {
            const float gm = __uint_as_float(wmax);
            #pragma unroll
            for (int j = PPT - 1; j >= 0; --j)
                if (pd[j] == gm) tidx = base + j;       // reverse scan -> first index
        }
        const unsigned wmin = __reduce_min_sync(0xffffffffu, (unsigned)tidx);
        if (bb == wmax && tidx == (int)wmin) {           // exactly one thread per warp
            #pragma unroll
            for (int j = 0; j < PPT; j++) {
                if (tidx == base + j) {
                    float lo, hi;
                    f2_unpack(lo, hi, xq[j >> 1]); s_cand[wid][0] = (j & 1) ? hi : lo;
                    f2_unpack(lo, hi, yq[j >> 1]); s_cand[wid][1] = (j & 1) ? hi : lo;
                    f2_unpack(lo, hi, zq[j >> 1]); s_cand[wid][2] = (j & 1) ? hi : lo;
                }
            }
        }
        if (lane == 0) { s_wv[wid] = wmax; s_wi[wid] = (int)wmin; }
        __syncthreads();

        if (wid == 0) {
            const unsigned bits = (lane < 16) ? s_wv[lane] : 0u;
            const unsigned idx  = (lane < 16) ? (unsigned)s_wi[lane] : 0xffffffffu;
            const unsigned m    = __reduce_max_sync(0xffffffffu, bits);
            const unsigned cidx = __reduce_min_sync(0xffffffffu, (bits == m) ? idx : 0xffffffffu);
            const unsigned wl   = __reduce_min_sync(0xffffffffu,
                                    (bits == m && idx == cidx) ? (unsigned)lane : 32u);
            const float wx = s_cand[wl][0];
            const float wy = s_cand[wl][1];
            const float wz = s_cand[wl][2];

            if (lane < CLUSTER) {
                const uint32_t loc = smem_u32(&mbox[it & 1][rank][0]);
                uint32_t rem;
                asm("mapa.shared::cluster.u32 %0, %1, %2;" : "=r"(rem) : "r"(loc), "r"(lane));
                unsigned long long a = ((unsigned long long)cidx << 32) | m;
                unsigned long long c = ((unsigned long long)__float_as_uint(wy) << 32)
                                      | __float_as_uint(wx);
                asm volatile("st.shared::cluster.b64 [%0], %1;"     :: "r"(rem),      "l"(a) : "memory");
                asm volatile("st.shared::cluster.b64 [%0+8], %1;"   :: "r"(rem),      "l"(c) : "memory");
                asm volatile("st.shared::cluster.b32 [%0+16], %1;"  :: "r"(rem),
                             "r"(__float_as_uint(wz)) : "memory");
            }
        }

        asm volatile("barrier.cluster.arrive.aligned;" ::: "memory");
        asm volatile("barrier.cluster.wait.aligned;"   ::: "memory");

        // every thread reduces the 8 mailbox entries (LDS broadcasts)
        unsigned bbits = 0u, bidx = 0xffffffffu, bx = 0, by = 0, bz = 0;
        #pragma unroll
        for (int r = 0; r < CLUSTER; r++) {
            const unsigned mb = mbox[it & 1][r][0];
            const unsigned mi = mbox[it & 1][r][1];
            const bool take = (mb > bbits) || (mb == bbits && mi < bidx);
            if (take) {
                bbits = mb; bidx = mi;
                bx = mbox[it & 1][r][2];
                by = mbox[it & 1][r][3];
                bz = mbox[it & 1][r][4];
            }
        }
        cx = __uint_as_float(bx);
        cy = __uint_as_float(by);
        cz = __uint_as_float(bz);

        if (rank == 0 && t == 0) {
            float* o = out_newxyz + ((size_t)b * NPT + it + 1) * 3;
            o[0] = cx; o[1] = cy; o[2] = cz;
        }
    }
}

// =================================================================================
// Kernel 2: feature transpose (B,C,N) -> (B,N,C), tiled 32x32 through smem.
// =================================================================================
__global__ void __launch_bounds__(256)
transpose_kernel(const float* __restrict__ feat)
{
    __shared__ float tile[32][33];
    const int b  = blockIdx.z;
    const int n0 = blockIdx.x * 32;
    const int c0 = blockIdx.y * 32;
    const int tx = threadIdx.x, ty = threadIdx.y;

    const float* src = feat + (size_t)b * NCH * N_PTS;
    #pragma unroll
    for (int i = 0; i < 32; i += 8)
        tile[ty + i][tx] = src[(size_t)(c0 + ty + i) * N_PTS + n0 + tx];
    __syncthreads();

    float* dst = g_featT + (size_t)b * N_PTS * NCH;
    #pragma unroll
    for (int i = 0; i < 32; i += 8)
        dst[(size_t)(n0 + ty + i) * NCH + c0 + tx] = tile[tx][ty + i];
}

// =================================================================================
// Kernel 3: ball query — one warp per centroid, early exit after K found.
// Distance matches the reference's expanded form: d = ((-2*dot) + s2) + n2.
// Qualify iff !(d > r^2); first K in index order; pad with first.
// =================================================================================
__global__ void __launch_bounds__(256)
ball_kernel(const float* __restrict__ xyz, const float* __restrict__ newxyz)
{
    const int wig    = (blockIdx.x * 256 + threadIdx.x) >> 5;   // b*512 + s
    const int lane   = threadIdx.x & 31;
    const int wlocal = threadIdx.x >> 5;
    __shared__ int sid[8][KNB];

    const int b = wig >> 9;
    const float* C = newxyz + (size_t)wig * 3;
    const float cx = C[0], cy = C[1], cz = C[2];
    const float s2 = __fadd_rn(__fadd_rn(__fmul_rn(cx,cx), __fmul_rn(cy,cy)), __fmul_rn(cz,cz));

    const float* X  = xyz  + (size_t)b * N_PTS * 3;
    const float* NN = g_n2 + (size_t)b * N_PTS;

    int cnt = 0;
    for (int basep = 0; basep < N_PTS && cnt < KNB; basep += 32) {
        const int p = basep + lane;
        const float x = X[3*p], y = X[3*p+1], z = X[3*p+2];
        float dot = __fmul_rn(cx, x);
        dot = __fmaf_rn(cy, y, dot);
        dot = __fmaf_rn(cz, z, dot);
        const float d = __fadd_rn(__fadd_rn(__fmul_rn(-2.0f, dot), s2), NN[p]);
        const bool q = !(d > R2);
        const unsigned m = __ballot_sync(0xffffffffu, q);
        const int pos = cnt + __popc(m & ((1u << lane) - 1u));
        if (q && pos < KNB) sid[wlocal][pos] = p;
        cnt += __popc(m);
    }
    __syncwarp();

    const int first = sid[wlocal][0];          // cnt==0 impossible: centroid itself qualifies
    const int v = (lane < cnt) ? sid[wlocal][lane] : first;
    g_idx[(size_t)wig * KNB + lane] = v;
}

// =================================================================================
// Kernel 4: masked max pool from transposed features — block per (b,s), thread=c.
// Warp lanes read consecutive channels -> fully coalesced 128B gathers.
// =================================================================================
__global__ void __launch_bounds__(128)
pool_kernel(float* __restrict__ out)
{
    const int g = blockIdx.x;             // b*512 + s
    const int c = threadIdx.x;
    const int b = g >> 9;
    const int s = g & 511;

    __shared__ int nb[KNB];
    if (c < KNB) nb[c] = g_idx[(size_t)g * KNB + c];
    __syncthreads();

    const float* F = g_featT + (size_t)b * N_PTS * NCH;

    float m0 = F[(size_t)nb[0] * NCH + c];
    float m1 = F[(size_t)nb[1] * NCH + c];
    float m2 = F[(size_t)nb[2] * NCH + c];
    float m3 = F[(size_t)nb[3] * NCH + c];
    #pragma unroll
    for (int k = 4; k < KNB; k += 4) {
        m0 = fmaxf(m0, F[(size_t)nb[k]   * NCH + c]);
        m1 = fmaxf(m1, F[(size_t)nb[k+1] * NCH + c]);
        m2 = fmaxf(m2, F[(size_t)nb[k+2] * NCH + c]);
        m3 = fmaxf(m3, F[(size_t)nb[k+3] * NCH + c]);
    }
    const float m = fmaxf(fmaxf(m0, m1), fmaxf(m2, m3));

    out[(size_t)B_SZ*NPT*3 + ((size_t)b * NCH + c) * NPT + s] = m;
}

// =================================================================================
extern "C" void kernel_launch(void* const* d_in, const int* in_sizes, int n_in,
                              void* d_out, int out_size)
{
    const float* xyz  = (const float*)d_in[0];   // (8, 16384, 3) fp32
    const float* feat = (const float*)d_in[1];   // (8, 128, 16384) fp32
    float* out = (float*)d_out;                  // new_xyz (12288) ++ sub_features (524288)

    dim3 tgrid(N_PTS / 32, NCH / 32, B_SZ);
    dim3 tblk(32, 8);
    transpose_kernel<<<tgrid, tblk>>>(feat);

    dim3 fgrid(CLUSTER, B_SZ);
    fps_kernel<<<fgrid, FPS_THR>>>(xyz, out);

    ball_kernel<<<(B_SZ * NPT * 32) / 256, 256>>>(xyz, out);
    pool_kernel<<<B_SZ * NPT, 128>>>(out);
}